// round 1
// baseline (speedup 1.0000x reference)
#include <cuda_runtime.h>
#include <math.h>

// Problem constants
#define SS 2048
#define BB 32
#define DD 256
#define HH 4
#define NN (SS*BB)          // 65536 rows
#define EPS 1e-5f

// GEMM tiling
#define BM  128
#define BN_ 128
#define BK  32
#define SA  132             // padded SMEM row stride (16B-aligned rows)

// ---------------- scratch (static device globals; no allocations) ----------
// 8 buffers of [N, D] fp32: Q ping/pong, K ping/pong, V ping/pong, T1, T2
__device__ float g_buf[(size_t)8 * NN * DD];          // 512 MB
__device__ float g_psum[256][2][DD];                  // per-slab (sum, sumsq)
__device__ float g_scale[DD];
__device__ float g_shift[DD];
__device__ float g_sm_m[32][BB][DD];                  // softmax chunk partials
__device__ float g_sm_l[32][BB][DD];
__device__ float g_sm_a[32][BB][DD];
__device__ float g_headout[BB][HH*DD];
__device__ float g_mlp0[BB][DD];
__device__ float g_mlp1[BB][DD];

// ---------------------------------------------------------------------------
// GEMM: C[N,256] = f(A)[N,256] @ W[256,256]^T + bias
//   MODE 0: f(A)      = A1
//   MODE 1: f(A)[n,e] = relu((A1[n,e]-A2[n,e])*scale[e] + shift[e])   (k - q)
//   MODE 2: f(A)[n,e] = relu( A1[n,e]*scale[e] + shift[e])
// 128x128 block tile, 8x8 per-thread tile, BK=32, single SMEM buffer with
// register prefetch of the next K-chunk issued before the compute phase.
// ---------------------------------------------------------------------------
template<int MODE>
__global__ void __launch_bounds__(256, 2)
gemm_k(const float* __restrict__ A1, const float* __restrict__ A2,
       const float* __restrict__ W,  const float* __restrict__ bias,
       float* __restrict__ C)
{
    __shared__ float As[BK][SA];
    __shared__ float Ws[BK][SA];
    __shared__ float s_scale[DD];
    __shared__ float s_shift[DD];

    const int tid = threadIdx.x;
    const int n0  = blockIdx.x * BM;
    const int c0  = blockIdx.y * BN_;

    if (MODE != 0) {
        for (int i = tid; i < DD; i += 256) {
            s_scale[i] = g_scale[i];
            s_shift[i] = g_shift[i];
        }
    }
    __syncthreads();

    // load mapping: 256 threads cover 128 rows x 32 cols as float4 along K
    const int lr = tid >> 3;            // 0..31 (+= 32 per i)
    const int lc = (tid & 7) << 2;      // 0,4,...,28

    float4 ra[4], rw[4];

    auto fetch = [&](int kc) {
        #pragma unroll
        for (int i = 0; i < 4; ++i) {
            const int row = n0 + lr + i*32;
            const int col = kc + lc;
            float4 v = *(const float4*)(A1 + (size_t)row*DD + col);
            if (MODE == 1) {
                float4 v2 = *(const float4*)(A2 + (size_t)row*DD + col);
                v.x -= v2.x; v.y -= v2.y; v.z -= v2.z; v.w -= v2.w;
            }
            if (MODE != 0) {
                v.x = fmaxf(fmaf(v.x, s_scale[col+0], s_shift[col+0]), 0.f);
                v.y = fmaxf(fmaf(v.y, s_scale[col+1], s_shift[col+1]), 0.f);
                v.z = fmaxf(fmaf(v.z, s_scale[col+2], s_shift[col+2]), 0.f);
                v.w = fmaxf(fmaf(v.w, s_scale[col+3], s_shift[col+3]), 0.f);
            }
            ra[i] = v;
            const int wrow = c0 + lr + i*32;
            rw[i] = *(const float4*)(W + (size_t)wrow*DD + kc + lc);
        }
    };
    auto store = [&]() {
        #pragma unroll
        for (int i = 0; i < 4; ++i) {
            const int n = lr + i*32;
            As[lc+0][n] = ra[i].x;  As[lc+1][n] = ra[i].y;
            As[lc+2][n] = ra[i].z;  As[lc+3][n] = ra[i].w;
            Ws[lc+0][n] = rw[i].x;  Ws[lc+1][n] = rw[i].y;
            Ws[lc+2][n] = rw[i].z;  Ws[lc+3][n] = rw[i].w;
        }
    };

    float acc[8][8];
    #pragma unroll
    for (int i = 0; i < 8; ++i)
        #pragma unroll
        for (int j = 0; j < 8; ++j) acc[i][j] = 0.f;

    const int tr = (tid >> 4) << 3;     // row offset within tile
    const int tc = (tid & 15) << 3;     // col offset within tile

    fetch(0);
    for (int ch = 0; ch < DD/BK; ++ch) {
        store();
        __syncthreads();
        if (ch + 1 < DD/BK) fetch((ch+1)*BK);  // LDGs overlap compute below
        #pragma unroll
        for (int kk = 0; kk < BK; ++kk) {
            float4 a0 = *(const float4*)&As[kk][tr];
            float4 a1 = *(const float4*)&As[kk][tr+4];
            float4 b0 = *(const float4*)&Ws[kk][tc];
            float4 b1 = *(const float4*)&Ws[kk][tc+4];
            float av[8] = {a0.x,a0.y,a0.z,a0.w,a1.x,a1.y,a1.z,a1.w};
            float bv[8] = {b0.x,b0.y,b0.z,b0.w,b1.x,b1.y,b1.z,b1.w};
            #pragma unroll
            for (int i = 0; i < 8; ++i)
                #pragma unroll
                for (int j = 0; j < 8; ++j)
                    acc[i][j] = fmaf(av[i], bv[j], acc[i][j]);
        }
        __syncthreads();
    }

    float bb[8];
    #pragma unroll
    for (int j = 0; j < 8; ++j) bb[j] = bias[c0 + tc + j];
    #pragma unroll
    for (int i = 0; i < 8; ++i) {
        float* cp = C + (size_t)(n0 + tr + i)*DD + c0 + tc;
        float4 o0 = {acc[i][0]+bb[0], acc[i][1]+bb[1], acc[i][2]+bb[2], acc[i][3]+bb[3]};
        float4 o1 = {acc[i][4]+bb[4], acc[i][5]+bb[5], acc[i][6]+bb[6], acc[i][7]+bb[7]};
        *(float4*)cp     = o0;
        *(float4*)(cp+4) = o1;
    }
}

// ---------------------------------------------------------------------------
// BN stats: per-channel sum / sumsq over N rows of X1 (or X1-X2 when DIFF)
// Deterministic 2-level reduction: 256 slabs of 256 rows -> finalize kernel.
// ---------------------------------------------------------------------------
template<int DIFF>
__global__ void stats_part_k(const float* __restrict__ X1, const float* __restrict__ X2)
{
    const int slab = blockIdx.x;
    const int t = threadIdx.x;
    const size_t base = (size_t)slab * 256 * DD + t;
    float s = 0.f, sq = 0.f;
    #pragma unroll 4
    for (int r = 0; r < 256; ++r) {
        float x = X1[base + (size_t)r*DD];
        if (DIFF) x -= X2[base + (size_t)r*DD];
        s += x; sq += x*x;
    }
    g_psum[slab][0][t] = s;
    g_psum[slab][1][t] = sq;
}

__global__ void stats_final_k(const float* __restrict__ gamma, const float* __restrict__ beta)
{
    const int t = threadIdx.x;
    float s = 0.f, sq = 0.f;
    for (int c = 0; c < 256; ++c) { s += g_psum[c][0][t]; sq += g_psum[c][1][t]; }
    const float inv = 1.f / (float)NN;
    const float mean = s * inv;
    const float var  = sq * inv - mean * mean;       // biased, matches jnp.var
    const float sc   = rsqrtf(var + EPS) * gamma[t];
    g_scale[t] = sc;
    g_shift[t] = beta[t] - mean * sc;
}

// ---------------------------------------------------------------------------
// Softmax over S fused with V-weighted sum, online (m, l, acc) per (b,d).
// Stage 1: 32 S-chunks of 64 rows -> partials.  Stage 2: combine + write head.
// ---------------------------------------------------------------------------
__global__ void softmax_part_k(const float* __restrict__ W2, const float* __restrict__ V)
{
    const int b  = blockIdx.x;
    const int ch = blockIdx.y;
    const int d  = threadIdx.x;
    const size_t stride = (size_t)BB * DD;
    size_t off = (size_t)(ch*64)*stride + (size_t)b*DD + d;
    float m = -INFINITY, l = 0.f, a = 0.f;
    for (int s = 0; s < 64; ++s) {
        const float w  = W2[off];
        const float vv = V[off];
        const float nm = fmaxf(m, w);
        const float e1 = expf(m - nm);
        const float e2 = expf(w - nm);
        l = l*e1 + e2;
        a = a*e1 + e2*vv;
        m = nm;
        off += stride;
    }
    g_sm_m[ch][b][d] = m;
    g_sm_l[ch][b][d] = l;
    g_sm_a[ch][b][d] = a;
}

__global__ void softmax_final_k(int head)
{
    const int b = blockIdx.x;
    const int d = threadIdx.x;
    float M = -INFINITY;
    #pragma unroll
    for (int c = 0; c < 32; ++c) M = fmaxf(M, g_sm_m[c][b][d]);
    float L = 0.f, A = 0.f;
    #pragma unroll
    for (int c = 0; c < 32; ++c) {
        const float e = expf(g_sm_m[c][b][d] - M);
        L += g_sm_l[c][b][d] * e;
        A += g_sm_a[c][b][d] * e;
    }
    g_headout[b][head*DD + d] = A / L;
}

// ---------------------------------------------------------------------------
// Final MLP layers (tiny): out[b,j] = act(sum_e X[b,e] * W[j,e] + bias[j])
// One block per output channel j; W row staged in SMEM; warp-reduce per b.
// ---------------------------------------------------------------------------
template<bool RELU, int E>
__global__ void mlp_k(const float* __restrict__ X, const float* __restrict__ W,
                      const float* __restrict__ bias, float* __restrict__ out)
{
    __shared__ float sw[E];
    __shared__ float red[4];
    const int j = blockIdx.x;
    const int t = threadIdx.x;
    for (int e = t; e < E; e += 128) sw[e] = W[(size_t)j*E + e];
    __syncthreads();
    for (int b = 0; b < BB; ++b) {
        float p = 0.f;
        for (int e = t; e < E; e += 128) p += X[(size_t)b*E + e] * sw[e];
        #pragma unroll
        for (int o = 16; o; o >>= 1) p += __shfl_xor_sync(0xffffffffu, p, o);
        if ((t & 31) == 0) red[t >> 5] = p;
        __syncthreads();
        if (t == 0) {
            float r = red[0] + red[1] + red[2] + red[3] + bias[j];
            if (RELU) r = fmaxf(r, 0.f);
            out[(size_t)b*DD + j] = r;
        }
        __syncthreads();
    }
}

// ---------------------------------------------------------------------------
extern "C" void kernel_launch(void* const* d_in, const int* in_sizes, int n_in,
                              void* d_out, int out_size)
{
    (void)in_sizes; (void)n_in; (void)out_size;
    const float* q   = (const float*)d_in[0];
    const float* k   = (const float*)d_in[1];
    const float* v   = (const float*)d_in[2];
    const float* wq  = (const float*)d_in[3];
    const float* bq  = (const float*)d_in[4];
    const float* wk  = (const float*)d_in[5];
    const float* bk  = (const float*)d_in[6];
    const float* wv  = (const float*)d_in[7];
    const float* bv  = (const float*)d_in[8];
    const float* g1  = (const float*)d_in[9];
    const float* be1 = (const float*)d_in[10];
    const float* wl1 = (const float*)d_in[11];
    const float* bl1 = (const float*)d_in[12];
    const float* g2  = (const float*)d_in[13];
    const float* be2 = (const float*)d_in[14];
    const float* wl2 = (const float*)d_in[15];
    const float* bl2 = (const float*)d_in[16];
    const float* mw0 = (const float*)d_in[17];
    const float* mb0 = (const float*)d_in[18];
    const float* mw1 = (const float*)d_in[19];
    const float* mb1 = (const float*)d_in[20];
    const float* mw2 = (const float*)d_in[21];
    const float* mb2 = (const float*)d_in[22];
    float* out = (float*)d_out;

    float *buf = nullptr, *headout = nullptr, *m0 = nullptr, *m1 = nullptr;
    cudaGetSymbolAddress((void**)&buf,     g_buf);
    cudaGetSymbolAddress((void**)&headout, g_headout);
    cudaGetSymbolAddress((void**)&m0,      g_mlp0);
    cudaGetSymbolAddress((void**)&m1,      g_mlp1);

    const size_t SZ = (size_t)NN * DD;
    dim3 ggrid(NN/BM, DD/BN_);

    const float* Qc = q; const float* Kc = k; const float* Vc = v;
    for (int h = 0; h < HH; ++h) {
        float* Qn = buf + (size_t)(0 + (h & 1)) * SZ;
        float* Kn = buf + (size_t)(2 + (h & 1)) * SZ;
        float* Vn = buf + (size_t)(4 + (h & 1)) * SZ;
        float* T1 = buf + 6 * SZ;
        float* T2 = buf + 7 * SZ;

        // chained per-head projections
        gemm_k<0><<<ggrid, 256>>>(Qc, nullptr, wq + (size_t)h*DD*DD, bq + h*DD, Qn);
        gemm_k<0><<<ggrid, 256>>>(Kc, nullptr, wk + (size_t)h*DD*DD, bk + h*DD, Kn);
        gemm_k<0><<<ggrid, 256>>>(Vc, nullptr, wv + (size_t)h*DD*DD, bv + h*DD, Vn);

        // BN1 stats on (K-Q), then fused relu(bn(K-Q)) @ wl1^T + bl1
        stats_part_k<1><<<256, 256>>>(Kn, Qn);
        stats_final_k<<<1, 256>>>(g1 + h*DD, be1 + h*DD);
        gemm_k<1><<<ggrid, 256>>>(Kn, Qn, wl1 + (size_t)h*DD*DD, bl1 + h*DD, T1);

        // BN2 stats on T1, then fused relu(bn(T1)) @ wl2^T + bl2
        stats_part_k<0><<<256, 256>>>(T1, nullptr);
        stats_final_k<<<1, 256>>>(g2 + h*DD, be2 + h*DD);
        gemm_k<2><<<ggrid, 256>>>(T1, nullptr, wl2 + (size_t)h*DD*DD, bl2 + h*DD, T2);

        // softmax over S fused with V-weighted sum
        softmax_part_k<<<dim3(BB, 32), DD>>>(T2, Vn);
        softmax_final_k<<<BB, DD>>>(h);

        Qc = Qn; Kc = Kn; Vc = Vn;
    }

    // final MLP: [B,1024] -> 256 -> 256 -> 256
    mlp_k<true,  HH*DD><<<DD, 128>>>(headout, mw0, mb0, m0);
    mlp_k<true,  DD   ><<<DD, 128>>>(m0,      mw1, mb1, m1);
    mlp_k<false, DD   ><<<DD, 128>>>(m1,      mw2, mb2, out);
}

// round 4
// speedup vs baseline: 1.8817x; 1.8817x over previous
#include <cuda_runtime.h>
#include <cuda_bf16.h>
#include <math.h>
#include <stdint.h>

#define SS 2048
#define BB 32
#define DD 256
#define HH 4
#define NROWS (SS*BB)          // 65536
#define EPS 1e-5f

// ---------------- scratch (static device globals; no allocations) ----------
__device__ float g_buf[(size_t)8 * NROWS * DD];        // ping/pong Q,K,V + T1,T2
__device__ float g_psum[1024][2][DD];
__device__ float g_scale[DD];
__device__ float g_shift[DD];
__device__ float g_sm_m[64][BB][DD];
__device__ float g_sm_l[64][BB][DD];
__device__ float g_sm_a[64][BB][DD];
__device__ float g_headout[BB][HH*DD];
__device__ float g_mlp0[BB][DD];
__device__ float g_mlp1[BB][DD];
__device__ __nv_bfloat16 g_whi[20][DD*DD];             // 5 weights x 4 heads, hi
__device__ __nv_bfloat16 g_wlo[20][DD*DD];             // lo (fp32 remainder)

// ======================= helpers ==========================================
__device__ __forceinline__ uint32_t smem_u32(const void* p) {
    uint32_t a;
    asm("{ .reg .u64 t; cvta.to.shared.u64 t, %1; cvt.u32.u64 %0, t; }"
        : "=r"(a) : "l"(p));
    return a;
}
// swizzle for 64-byte rows: spreads the 8 16B-chunks of 8 consecutive rows
// across all 8 bank-groups of a 128B line.
__device__ __forceinline__ uint32_t swz(uint32_t off) {
    return off ^ ((off >> 3) & 0x30);
}
__device__ __forceinline__ void ldsm4(uint32_t& r0, uint32_t& r1,
                                      uint32_t& r2, uint32_t& r3, uint32_t addr) {
    asm volatile("ldmatrix.sync.aligned.m8n8.x4.shared.b16 {%0,%1,%2,%3}, [%4];"
                 : "=r"(r0), "=r"(r1), "=r"(r2), "=r"(r3) : "r"(addr));
}
__device__ __forceinline__ void mma_bf16(float* d, const uint32_t* a,
                                         uint32_t b0, uint32_t b1) {
    asm volatile(
        "mma.sync.aligned.m16n8k16.row.col.f32.bf16.bf16.f32 "
        "{%0,%1,%2,%3},{%4,%5,%6,%7},{%8,%9},{%0,%1,%2,%3};"
        : "+f"(d[0]), "+f"(d[1]), "+f"(d[2]), "+f"(d[3])
        : "r"(a[0]), "r"(a[1]), "r"(a[2]), "r"(a[3]), "r"(b0), "r"(b1));
}
__device__ __forceinline__ unsigned short bf_hi(float x, float& rem) {
    __nv_bfloat16 h = __float2bfloat16_rn(x);
    rem = x - __bfloat162float(h);
    return __bfloat16_as_ushort(h);
}
__device__ __forceinline__ unsigned short bf_rn(float x) {
    return __bfloat16_as_ushort(__float2bfloat16_rn(x));
}

// ===========================================================================
// Weight pre-split: fp32 -> bf16 hi/lo.  slot = head*5 + {wq,wk,wv,wl1,wl2}
// ===========================================================================
__global__ void wconv_k(const float* __restrict__ wq, const float* __restrict__ wk,
                        const float* __restrict__ wv, const float* __restrict__ wl1,
                        const float* __restrict__ wl2)
{
    int idx = blockIdx.x * blockDim.x + threadIdx.x;   // 5 * 4 * 65536
    int t = idx >> 18;
    int r = idx & 0x3FFFF;
    const float* src = (t == 0 ? wq : t == 1 ? wk : t == 2 ? wv : t == 3 ? wl1 : wl2);
    float x = src[r];
    int h = r >> 16;
    int e = r & 0xFFFF;
    int slot = h * 5 + t;
    float rem;
    unsigned short hi = bf_hi(x, rem);
    g_whi[slot][e] = __ushort_as_bfloat16(hi);
    g_wlo[slot][e] = __ushort_as_bfloat16(bf_rn(rem));
}

// ===========================================================================
// HMMA GEMM: C[N,256] = f(A)[N,256] @ W[256,256]^T + bias   (split bf16 x3)
//   MODE 0: f = identity
//   MODE 1: f = relu((A1-A2)*scale + shift)
//   MODE 2: f = relu(A1*scale + shift)
// CTA 128x128, BK=32, 8 warps (4M x 2N -> 32x64 warp tiles), TN mma.sync,
// register-prefetch software pipeline, swizzled SMEM for conflict-free ldmatrix.
// ===========================================================================
#define BM 128
#define BN 128
#define BK 32

template<int MODE>
__global__ void __launch_bounds__(256, 1)
gemm_mma(const float* __restrict__ A1, const float* __restrict__ A2,
         const __nv_bfloat16* __restrict__ Whi, const __nv_bfloat16* __restrict__ Wlo,
         const float* __restrict__ bias, float* __restrict__ C)
{
    __shared__ __align__(1024) __nv_bfloat16 sAh[BM*BK];
    __shared__ __align__(1024) __nv_bfloat16 sAl[BM*BK];
    __shared__ __align__(1024) __nv_bfloat16 sWh[BN*BK];
    __shared__ __align__(1024) __nv_bfloat16 sWl[BN*BK];
    __shared__ float s_bias[BN];
    __shared__ float s_scale[DD];
    __shared__ float s_shift[DD];

    const int tid = threadIdx.x;
    const int n0 = blockIdx.x * BM;
    const int c0 = blockIdx.y * BN;

    if (tid < BN) s_bias[tid] = bias[c0 + tid];
    if (MODE != 0 && tid < DD) { s_scale[tid] = g_scale[tid]; s_shift[tid] = g_shift[tid]; }
    __syncthreads();

    // ---- global->reg fetch (A: fp32 with MODE transform; W: bf16 hi/lo) ----
    const int lr = tid >> 3;              // A rows 0..31 (+32 per i)
    const int lc = (tid & 7) << 2;        // A col group (4 floats)
    const int wr = tid >> 1;              // W row 0..127
    const int wh_ = tid & 1;              // W 16-elem half of the 32-col chunk
    float4 ra[4];
    uint4  rwh[2], rwl[2];

    auto fetchA = [&](int kc) {
        #pragma unroll
        for (int i = 0; i < 4; ++i) {
            const size_t gof = (size_t)(n0 + lr + i*32) * DD + kc + lc;
            float4 v = *(const float4*)(A1 + gof);
            if (MODE == 1) {
                float4 v2 = *(const float4*)(A2 + gof);
                v.x -= v2.x; v.y -= v2.y; v.z -= v2.z; v.w -= v2.w;
            }
            if (MODE != 0) {
                const int cc = kc + lc;
                v.x = fmaxf(fmaf(v.x, s_scale[cc+0], s_shift[cc+0]), 0.f);
                v.y = fmaxf(fmaf(v.y, s_scale[cc+1], s_shift[cc+1]), 0.f);
                v.z = fmaxf(fmaf(v.z, s_scale[cc+2], s_shift[cc+2]), 0.f);
                v.w = fmaxf(fmaf(v.w, s_scale[cc+3], s_shift[cc+3]), 0.f);
            }
            ra[i] = v;
        }
    };
    auto fetchW = [&](int kc) {
        const __nv_bfloat16* ph = Whi + (size_t)(c0 + wr) * DD + kc + wh_*16;
        const __nv_bfloat16* pl = Wlo + (size_t)(c0 + wr) * DD + kc + wh_*16;
        rwh[0] = *(const uint4*)ph;       rwh[1] = *(const uint4*)(ph + 8);
        rwl[0] = *(const uint4*)pl;       rwl[1] = *(const uint4*)(pl + 8);
    };
    auto store = [&]() {
        #pragma unroll
        for (int i = 0; i < 4; ++i) {
            float4 v = ra[i];
            float r0, r1, r2, r3;
            unsigned int h01 = bf_hi(v.x, r0) | ((unsigned int)bf_hi(v.y, r1) << 16);
            unsigned int h23 = bf_hi(v.z, r2) | ((unsigned int)bf_hi(v.w, r3) << 16);
            unsigned int l01 = bf_rn(r0) | ((unsigned int)bf_rn(r1) << 16);
            unsigned int l23 = bf_rn(r2) | ((unsigned int)bf_rn(r3) << 16);
            const uint32_t so = swz((uint32_t)((lr + i*32) * 64 + lc * 2));
            *(uint2*)((char*)sAh + so) = make_uint2(h01, h23);
            *(uint2*)((char*)sAl + so) = make_uint2(l01, l23);
        }
        const uint32_t so0 = swz((uint32_t)(wr * 64 + wh_*32));
        const uint32_t so1 = swz((uint32_t)(wr * 64 + wh_*32 + 16));
        *(uint4*)((char*)sWh + so0) = rwh[0];
        *(uint4*)((char*)sWh + so1) = rwh[1];
        *(uint4*)((char*)sWl + so0) = rwl[0];
        *(uint4*)((char*)sWl + so1) = rwl[1];
    };

    // ---- per-warp mma state ----
    const int lane = tid & 31;
    const int wid  = tid >> 5;
    const int moff = (wid >> 1) * 32;     // warp M offset (4 warps)
    const int noff = (wid & 1) * 64;      // warp N offset (2 warps)

    const uint32_t aBaseH = smem_u32(sAh), aBaseL = smem_u32(sAl);
    const uint32_t wBaseH = smem_u32(sWh), wBaseL = smem_u32(sWl);

    // ldmatrix lane address components
    const uint32_t arow   = moff + (lane & 15);
    const uint32_t acol16 = (uint32_t)(lane >> 4) * 16;
    const uint32_t brow   = noff + (lane & 7) + ((lane >> 1) & 8);
    const uint32_t bcol16 = (uint32_t)((lane >> 3) & 1) * 16;

    float d[2][8][4];
    #pragma unroll
    for (int i = 0; i < 2; ++i)
        #pragma unroll
        for (int j = 0; j < 8; ++j)
            #pragma unroll
            for (int q = 0; q < 4; ++q) d[i][j][q] = 0.f;

    fetchA(0); fetchW(0);
    #pragma unroll 1
    for (int ch = 0; ch < DD/BK; ++ch) {
        store();
        __syncthreads();
        if (ch + 1 < DD/BK) { fetchA((ch+1)*BK); fetchW((ch+1)*BK); }

        #pragma unroll
        for (int ks = 0; ks < 2; ++ks) {
            uint32_t ah[2][4], al[2][4];
            #pragma unroll
            for (int mt = 0; mt < 2; ++mt) {
                const uint32_t ao = swz((arow + mt*16) * 64 + ks*32 + acol16);
                ldsm4(ah[mt][0], ah[mt][1], ah[mt][2], ah[mt][3], aBaseH + ao);
                ldsm4(al[mt][0], al[mt][1], al[mt][2], al[mt][3], aBaseL + ao);
            }
            #pragma unroll
            for (int ng = 0; ng < 4; ++ng) {
                const uint32_t bo = swz((brow + ng*16) * 64 + ks*32 + bcol16);
                uint32_t bh0, bh1, bh2, bh3, bl0, bl1, bl2, bl3;
                ldsm4(bh0, bh1, bh2, bh3, wBaseH + bo);
                ldsm4(bl0, bl1, bl2, bl3, wBaseL + bo);
                #pragma unroll
                for (int mt = 0; mt < 2; ++mt) {
                    mma_bf16(d[mt][ng*2+0], ah[mt], bh0, bh1);
                    mma_bf16(d[mt][ng*2+0], ah[mt], bl0, bl1);
                    mma_bf16(d[mt][ng*2+0], al[mt], bh0, bh1);
                    mma_bf16(d[mt][ng*2+1], ah[mt], bh2, bh3);
                    mma_bf16(d[mt][ng*2+1], ah[mt], bl2, bl3);
                    mma_bf16(d[mt][ng*2+1], al[mt], bh2, bh3);
                }
            }
        }
        __syncthreads();
    }

    // ---- epilogue: frags + bias -> fp32 global ----
    const int erow = lane >> 2;
    const int ecol = (lane & 3) * 2;
    #pragma unroll
    for (int mt = 0; mt < 2; ++mt) {
        #pragma unroll
        for (int nt = 0; nt < 8; ++nt) {
            const int lcol = noff + nt*8 + ecol;
            const float b0 = s_bias[lcol], b1 = s_bias[lcol + 1];
            float* base = C + (size_t)(n0 + moff + mt*16 + erow) * DD + c0 + lcol;
            float2 v0 = { d[mt][nt][0] + b0, d[mt][nt][1] + b1 };
            float2 v1 = { d[mt][nt][2] + b0, d[mt][nt][3] + b1 };
            *(float2*)base            = v0;
            *(float2*)(base + 8*DD)   = v1;
        }
    }
}

// ===========================================================================
// BN stats: 1024 slabs of 64 rows -> finalize
// ===========================================================================
template<int DIFF>
__global__ void stats_part_k(const float* __restrict__ X1, const float* __restrict__ X2)
{
    const int slab = blockIdx.x;
    const int t = threadIdx.x;
    const size_t base = (size_t)slab * 64 * DD + t;
    float s = 0.f, sq = 0.f;
    #pragma unroll 4
    for (int r = 0; r < 64; ++r) {
        float x = X1[base + (size_t)r * DD];
        if (DIFF) x -= X2[base + (size_t)r * DD];
        s += x; sq += x * x;
    }
    g_psum[slab][0][t] = s;
    g_psum[slab][1][t] = sq;
}

__global__ void stats_final_k(const float* __restrict__ gamma, const float* __restrict__ beta)
{
    const int t = threadIdx.x;
    float s = 0.f, sq = 0.f;
    for (int c = 0; c < 1024; ++c) { s += g_psum[c][0][t]; sq += g_psum[c][1][t]; }
    const float inv = 1.f / (float)NROWS;
    const float mean = s * inv;
    const float var  = sq * inv - mean * mean;
    const float sc   = rsqrtf(var + EPS) * gamma[t];
    g_scale[t] = sc;
    g_shift[t] = beta[t] - mean * sc;
}

// ===========================================================================
// Online softmax over S fused with V-weighted sum
// ===========================================================================
__global__ void softmax_part_k(const float* __restrict__ W2, const float* __restrict__ V)
{
    const int b  = blockIdx.x;
    const int ch = blockIdx.y;
    const int d  = threadIdx.x;
    const size_t stride = (size_t)BB * DD;
    size_t off = (size_t)(ch * 32) * stride + (size_t)b * DD + d;
    float m = -INFINITY, l = 0.f, a = 0.f;
    for (int s = 0; s < 32; ++s) {
        const float w  = W2[off];
        const float vv = V[off];
        const float nm = fmaxf(m, w);
        const float e1 = expf(m - nm);
        const float e2 = expf(w - nm);
        l = l * e1 + e2;
        a = a * e1 + e2 * vv;
        m = nm;
        off += stride;
    }
    g_sm_m[ch][b][d] = m;
    g_sm_l[ch][b][d] = l;
    g_sm_a[ch][b][d] = a;
}

__global__ void softmax_final_k(int head)
{
    const int b = blockIdx.x;
    const int d = threadIdx.x;
    float M = -INFINITY;
    #pragma unroll
    for (int c = 0; c < 64; ++c) M = fmaxf(M, g_sm_m[c][b][d]);
    float L = 0.f, A = 0.f;
    #pragma unroll
    for (int c = 0; c < 64; ++c) {
        const float e = expf(g_sm_m[c][b][d] - M);
        L += g_sm_l[c][b][d] * e;
        A += g_sm_a[c][b][d] * e;
    }
    g_headout[b][head * DD + d] = A / L;
}

// ===========================================================================
// Final tiny MLP
// ===========================================================================
template<bool RELU, int E>
__global__ void mlp_k(const float* __restrict__ X, const float* __restrict__ W,
                      const float* __restrict__ bias, float* __restrict__ out)
{
    __shared__ float sw[E];
    __shared__ float red[4];
    const int j = blockIdx.x;
    const int t = threadIdx.x;
    for (int e = t; e < E; e += 128) sw[e] = W[(size_t)j * E + e];
    __syncthreads();
    for (int b = 0; b < BB; ++b) {
        float p = 0.f;
        for (int e = t; e < E; e += 128) p += X[(size_t)b * E + e] * sw[e];
        #pragma unroll
        for (int o = 16; o; o >>= 1) p += __shfl_xor_sync(0xffffffffu, p, o);
        if ((t & 31) == 0) red[t >> 5] = p;
        __syncthreads();
        if (t == 0) {
            float r = red[0] + red[1] + red[2] + red[3] + bias[j];
            if (RELU) r = fmaxf(r, 0.f);
            out[(size_t)b * DD + j] = r;
        }
        __syncthreads();
    }
}

// ===========================================================================
extern "C" void kernel_launch(void* const* d_in, const int* in_sizes, int n_in,
                              void* d_out, int out_size)
{
    (void)in_sizes; (void)n_in; (void)out_size;
    const float* q   = (const float*)d_in[0];
    const float* k   = (const float*)d_in[1];
    const float* v   = (const float*)d_in[2];
    const float* wq  = (const float*)d_in[3];
    const float* bq  = (const float*)d_in[4];
    const float* wk  = (const float*)d_in[5];
    const float* bk  = (const float*)d_in[6];
    const float* wv  = (const float*)d_in[7];
    const float* bv  = (const float*)d_in[8];
    const float* g1  = (const float*)d_in[9];
    const float* be1 = (const float*)d_in[10];
    const float* wl1 = (const float*)d_in[11];
    const float* bl1 = (const float*)d_in[12];
    const float* g2  = (const float*)d_in[13];
    const float* be2 = (const float*)d_in[14];
    const float* wl2 = (const float*)d_in[15];
    const float* bl2 = (const float*)d_in[16];
    const float* mw0 = (const float*)d_in[17];
    const float* mb0 = (const float*)d_in[18];
    const float* mw1 = (const float*)d_in[19];
    const float* mb1 = (const float*)d_in[20];
    const float* mw2 = (const float*)d_in[21];
    const float* mb2 = (const float*)d_in[22];
    float* out = (float*)d_out;

    float *buf = nullptr, *headout = nullptr, *m0 = nullptr, *m1 = nullptr;
    __nv_bfloat16 *whi = nullptr, *wlo = nullptr;
    cudaGetSymbolAddress((void**)&buf,     g_buf);
    cudaGetSymbolAddress((void**)&headout, g_headout);
    cudaGetSymbolAddress((void**)&m0,      g_mlp0);
    cudaGetSymbolAddress((void**)&m1,      g_mlp1);
    cudaGetSymbolAddress((void**)&whi,     g_whi);
    cudaGetSymbolAddress((void**)&wlo,     g_wlo);

    const size_t SZ = (size_t)NROWS * DD;
    dim3 ggrid(NROWS / BM, DD / BN);     // (512, 2)

    // pre-split all 20 weight matrices to bf16 hi/lo
    wconv_k<<<(5 * HH * DD * DD) / 256, 256>>>(wq, wk, wv, wl1, wl2);

    const float* Qc = q; const float* Kc = k; const float* Vc = v;
    for (int h = 0; h < HH; ++h) {
        float* Qn = buf + (size_t)(0 + (h & 1)) * SZ;
        float* Kn = buf + (size_t)(2 + (h & 1)) * SZ;
        float* Vn = buf + (size_t)(4 + (h & 1)) * SZ;
        float* T1 = buf + 6 * SZ;
        float* T2 = buf + 7 * SZ;
        const size_t wsz = (size_t)DD * DD;
        const __nv_bfloat16* Wq_h = whi + (h*5 + 0) * wsz; const __nv_bfloat16* Wq_l = wlo + (h*5 + 0) * wsz;
        const __nv_bfloat16* Wk_h = whi + (h*5 + 1) * wsz; const __nv_bfloat16* Wk_l = wlo + (h*5 + 1) * wsz;
        const __nv_bfloat16* Wv_h = whi + (h*5 + 2) * wsz; const __nv_bfloat16* Wv_l = wlo + (h*5 + 2) * wsz;
        const __nv_bfloat16* W1_h = whi + (h*5 + 3) * wsz; const __nv_bfloat16* W1_l = wlo + (h*5 + 3) * wsz;
        const __nv_bfloat16* W2_h = whi + (h*5 + 4) * wsz; const __nv_bfloat16* W2_l = wlo + (h*5 + 4) * wsz;

        gemm_mma<0><<<ggrid, 256>>>(Qc, nullptr, Wq_h, Wq_l, bq + h*DD, Qn);
        gemm_mma<0><<<ggrid, 256>>>(Kc, nullptr, Wk_h, Wk_l, bk + h*DD, Kn);
        gemm_mma<0><<<ggrid, 256>>>(Vc, nullptr, Wv_h, Wv_l, bv + h*DD, Vn);

        stats_part_k<1><<<1024, 256>>>(Kn, Qn);
        stats_final_k<<<1, 256>>>(g1 + h*DD, be1 + h*DD);
        gemm_mma<1><<<ggrid, 256>>>(Kn, Qn, W1_h, W1_l, bl1 + h*DD, T1);

        stats_part_k<0><<<1024, 256>>>(T1, nullptr);
        stats_final_k<<<1, 256>>>(g2 + h*DD, be2 + h*DD);
        gemm_mma<2><<<ggrid, 256>>>(T1, nullptr, W2_h, W2_l, bl2 + h*DD, T2);

        softmax_part_k<<<dim3(BB, 64), DD>>>(T2, Vn);
        softmax_final_k<<<BB, DD>>>(h);

        Qc = Qn; Kc = Kn; Vc = Vn;
    }

    mlp_k<true,  HH*DD><<<DD, 128>>>(headout, mw0, mb0, m0);
    mlp_k<true,  DD   ><<<DD, 128>>>(m0,      mw1, mb1, m1);
    mlp_k<false, DD   ><<<DD, 128>>>(m1,      mw2, mb2, out);
}

// round 6
// speedup vs baseline: 2.3016x; 1.2232x over previous
#include <cuda_runtime.h>
#include <cuda_bf16.h>
#include <math.h>
#include <stdint.h>

#define SS 2048
#define BB 32
#define DD 256
#define HH 4
#define NROWS (SS*BB)          // 65536
#define EPS 1e-5f

// ---------------- scratch (static device globals; no allocations) ----------
__device__ float g_buf[(size_t)8 * NROWS * DD];        // ping/pong Q,K,V + T1,T2
__device__ float g_psum[512][2][DD];                   // per-CTA-row stats partials
__device__ float g_pmid[32][2][DD];
__device__ float g_scale[DD];
__device__ float g_shift[DD];
__device__ float g_sm_m[64][BB][DD];
__device__ float g_sm_l[64][BB][DD];
__device__ float g_sm_a[64][BB][DD];
__device__ float g_headout[BB][HH*DD];
__device__ float g_mlp0[BB][DD];
__device__ float g_mlp1[BB][DD];
__device__ __nv_bfloat16 g_whi[20][DD*DD];             // 5 weights x 4 heads, hi
__device__ __nv_bfloat16 g_wlo[20][DD*DD];             // lo (fp32 remainder)

// ======================= helpers ==========================================
__device__ __forceinline__ uint32_t smem_u32(const void* p) {
    uint32_t a;
    asm("{ .reg .u64 t; cvta.to.shared.u64 t, %1; cvt.u32.u64 %0, t; }"
        : "=r"(a) : "l"(p));
    return a;
}
__device__ __forceinline__ uint32_t swz(uint32_t off) {   // 64B-row swizzle
    return off ^ ((off >> 3) & 0x30);
}
__device__ __forceinline__ void ldsm4(uint32_t& r0, uint32_t& r1,
                                      uint32_t& r2, uint32_t& r3, uint32_t addr) {
    asm volatile("ldmatrix.sync.aligned.m8n8.x4.shared.b16 {%0,%1,%2,%3}, [%4];"
                 : "=r"(r0), "=r"(r1), "=r"(r2), "=r"(r3) : "r"(addr));
}
__device__ __forceinline__ void mma_bf16(float* d, const uint32_t* a,
                                         uint32_t b0, uint32_t b1) {
    asm volatile(
        "mma.sync.aligned.m16n8k16.row.col.f32.bf16.bf16.f32 "
        "{%0,%1,%2,%3},{%4,%5,%6,%7},{%8,%9},{%0,%1,%2,%3};"
        : "+f"(d[0]), "+f"(d[1]), "+f"(d[2]), "+f"(d[3])
        : "r"(a[0]), "r"(a[1]), "r"(a[2]), "r"(a[3]), "r"(b0), "r"(b1));
}
__device__ __forceinline__ void cpasync16(uint32_t dst, const void* src) {
    asm volatile("cp.async.ca.shared.global [%0], [%1], 16;" :: "r"(dst), "l"(src));
}
__device__ __forceinline__ unsigned short bf_hi(float x, float& rem) {
    __nv_bfloat16 h = __float2bfloat16_rn(x);
    rem = x - __bfloat162float(h);
    return __bfloat16_as_ushort(h);
}
__device__ __forceinline__ unsigned short bf_rn(float x) {
    return __bfloat16_as_ushort(__float2bfloat16_rn(x));
}

// ===========================================================================
// Weight pre-split: fp32 -> bf16 hi/lo.  slot = head*5 + {wq,wk,wv,wl1,wl2}
// ===========================================================================
__global__ void wconv_k(const float* __restrict__ wq, const float* __restrict__ wk,
                        const float* __restrict__ wv, const float* __restrict__ wl1,
                        const float* __restrict__ wl2)
{
    int idx = blockIdx.x * blockDim.x + threadIdx.x;
    int t = idx >> 18;
    int r = idx & 0x3FFFF;
    const float* src = (t == 0 ? wq : t == 1 ? wk : t == 2 ? wv : t == 3 ? wl1 : wl2);
    float x = src[r];
    int h = r >> 16;
    int e = r & 0xFFFF;
    int slot = h * 5 + t;
    float rem;
    unsigned short hi = bf_hi(x, rem);
    g_whi[slot][e] = __ushort_as_bfloat16(hi);
    g_wlo[slot][e] = __ushort_as_bfloat16(bf_rn(rem));
}

// ===========================================================================
// HMMA GEMM: C[N,256] = f(A)[N,256] @ W[256,256]^T + bias   (split bf16 x3)
//   MODE 0: f = identity;  MODE 1: relu((A1-A2)*scale+shift);  MODE 2: relu(A1*scale+shift)
//   STATS 0: none; 1: per-col sum/sumsq of output; 2: of (output - D2)
// CTA 128x64, 8 warps (4M x 2N, 32x32 warp tiles), 2-stage cp.async pipeline.
// Race-free ordering: all writes into stage s are issued AFTER the barrier
// that retired stage s's readers (prefetch is issued post-sync, pre-mma).
// ===========================================================================
#define BM 128
#define BNT 64
#define BK 32
#define NCH (DD/BK)            // 8

// dynamic smem layout
#define ST_SZ   24576          // per stage: Ah 8K, Al 8K, Wh 4K, Wl 4K
#define AH_OFF  0
#define AL_OFF  8192
#define WH_OFF  16384
#define WL_OFF  20480
#define BIAS_OFF   49152
#define SCALE_OFF  49408
#define SHIFT_OFF  50432
#define SSUM_OFF   51456
#define SSQ_OFF    52480
#define GSMEM      53504

template<int MODE, int STATS>
__global__ void __launch_bounds__(256, 2)
gemm_mma(const float* __restrict__ A1, const float* __restrict__ A2,
         const float* __restrict__ D2,
         const __nv_bfloat16* __restrict__ Whi, const __nv_bfloat16* __restrict__ Wlo,
         const float* __restrict__ bias, float* __restrict__ C)
{
    extern __shared__ __align__(1024) char smem[];
    const uint32_t sb = smem_u32(smem);
    const int tid  = threadIdx.x;
    const int lane = tid & 31;
    const int wid  = tid >> 5;
    const int n0 = blockIdx.x * BM;
    const int c0 = blockIdx.y * BNT;

    float* s_bias  = (float*)(smem + BIAS_OFF);
    float* s_scale = (float*)(smem + SCALE_OFF);
    float* s_shift = (float*)(smem + SHIFT_OFF);
    float* s_sum   = (float*)(smem + SSUM_OFF);   // [4][64]
    float* s_sq    = (float*)(smem + SSQ_OFF);    // [4][64]

    if (tid < BNT) s_bias[tid] = bias[c0 + tid];
    if (MODE != 0) { s_scale[tid] = g_scale[tid]; s_shift[tid] = g_shift[tid]; }
    __syncthreads();

    // ---- A fetch (fp32 + transform) ----
    const int lr = tid >> 3;              // rows 0..31 (+32 per i)
    const int lc = (tid & 7) << 2;        // col group (4 floats)
    float4 ra[4];
    auto fetchA = [&](int kc) {
        #pragma unroll
        for (int i = 0; i < 4; ++i) {
            const size_t gof = (size_t)(n0 + lr + i*32) * DD + kc + lc;
            float4 v = __ldg((const float4*)(A1 + gof));
            if (MODE == 1) {
                float4 v2 = __ldg((const float4*)(A2 + gof));
                v.x -= v2.x; v.y -= v2.y; v.z -= v2.z; v.w -= v2.w;
            }
            if (MODE != 0) {
                const int cc = kc + lc;
                v.x = fmaxf(fmaf(v.x, s_scale[cc+0], s_shift[cc+0]), 0.f);
                v.y = fmaxf(fmaf(v.y, s_scale[cc+1], s_shift[cc+1]), 0.f);
                v.z = fmaxf(fmaf(v.z, s_scale[cc+2], s_shift[cc+2]), 0.f);
                v.w = fmaxf(fmaf(v.w, s_scale[cc+3], s_shift[cc+3]), 0.f);
            }
            ra[i] = v;
        }
    };
    auto storeA = [&](int stg) {
        char* base = smem + stg * ST_SZ;
        #pragma unroll
        for (int i = 0; i < 4; ++i) {
            float4 v = ra[i];
            float r0, r1, r2, r3;
            unsigned int h01 = bf_hi(v.x, r0) | ((unsigned int)bf_hi(v.y, r1) << 16);
            unsigned int h23 = bf_hi(v.z, r2) | ((unsigned int)bf_hi(v.w, r3) << 16);
            unsigned int l01 = bf_rn(r0) | ((unsigned int)bf_rn(r1) << 16);
            unsigned int l23 = bf_rn(r2) | ((unsigned int)bf_rn(r3) << 16);
            const uint32_t so = swz((uint32_t)((lr + i*32) * 64 + lc * 2));
            *(uint2*)(base + AH_OFF + so) = make_uint2(h01, h23);
            *(uint2*)(base + AL_OFF + so) = make_uint2(l01, l23);
        }
    };
    // ---- W fetch via cp.async (64 rows x 32 bf16, hi & lo) ----
    const int wrow = tid >> 2;            // 0..63
    const int wch  = tid & 3;             // 16B chunk
    auto asyncW = [&](int kc, int stg) {
        const uint32_t so = swz((uint32_t)(wrow * 64 + wch * 16));
        cpasync16(sb + stg*ST_SZ + WH_OFF + so, Whi + (size_t)(c0 + wrow) * DD + kc + wch*8);
        cpasync16(sb + stg*ST_SZ + WL_OFF + so, Wlo + (size_t)(c0 + wrow) * DD + kc + wch*8);
    };

    // ---- per-warp mma state ----
    const int mw   = wid >> 1;            // 0..3
    const int nw   = wid & 1;             // 0..1
    const int moff = mw * 32;
    const int noff = nw * 32;
    const uint32_t arow   = moff + (lane & 15);
    const uint32_t acol16 = (uint32_t)(lane >> 4) * 16;
    const uint32_t brow   = noff + (lane & 7) + ((lane >> 1) & 8);
    const uint32_t bcol16 = (uint32_t)((lane >> 3) & 1) * 16;

    float d[2][4][4];
    #pragma unroll
    for (int i = 0; i < 2; ++i)
        #pragma unroll
        for (int j = 0; j < 4; ++j)
            #pragma unroll
            for (int q = 0; q < 4; ++q) d[i][j][q] = 0.f;

    // ---- prologue: chunk 0 into stage 0, fully ready before loop ----
    fetchA(0);
    asyncW(0, 0);
    asm volatile("cp.async.commit_group;");
    storeA(0);
    asm volatile("cp.async.wait_group 0;");
    __syncthreads();

    #pragma unroll 1
    for (int ch = 0; ch < NCH; ++ch) {
        const int cur = ch & 1;

        // Prefetch chunk ch+1 into stage cur^1. Issued AFTER the barrier that
        // ended iteration ch-1 (which retired all reads of stage cur^1) ⇒ safe.
        if (ch + 1 < NCH) {
            fetchA((ch+1) * BK);
            asyncW((ch+1) * BK, cur ^ 1);
            asm volatile("cp.async.commit_group;");
        }

        const uint32_t aBH = sb + cur*ST_SZ + AH_OFF;
        const uint32_t aBL = sb + cur*ST_SZ + AL_OFF;
        const uint32_t wBH = sb + cur*ST_SZ + WH_OFF;
        const uint32_t wBL = sb + cur*ST_SZ + WL_OFF;

        #pragma unroll
        for (int ks = 0; ks < 2; ++ks) {
            uint32_t ah[2][4], al[2][4];
            #pragma unroll
            for (int mt = 0; mt < 2; ++mt) {
                const uint32_t ao = swz((arow + mt*16) * 64 + ks*32 + acol16);
                ldsm4(ah[mt][0], ah[mt][1], ah[mt][2], ah[mt][3], aBH + ao);
                ldsm4(al[mt][0], al[mt][1], al[mt][2], al[mt][3], aBL + ao);
            }
            #pragma unroll
            for (int ng = 0; ng < 2; ++ng) {
                const uint32_t bo = swz((brow + ng*16) * 64 + ks*32 + bcol16);
                uint32_t bh0, bh1, bh2, bh3, bl0, bl1, bl2, bl3;
                ldsm4(bh0, bh1, bh2, bh3, wBH + bo);
                ldsm4(bl0, bl1, bl2, bl3, wBL + bo);
                #pragma unroll
                for (int mt = 0; mt < 2; ++mt) {
                    mma_bf16(d[mt][ng*2+0], ah[mt], bh0, bh1);
                    mma_bf16(d[mt][ng*2+0], ah[mt], bl0, bl1);
                    mma_bf16(d[mt][ng*2+0], al[mt], bh0, bh1);
                    mma_bf16(d[mt][ng*2+1], ah[mt], bh2, bh3);
                    mma_bf16(d[mt][ng*2+1], ah[mt], bl2, bl3);
                    mma_bf16(d[mt][ng*2+1], al[mt], bh2, bh3);
                }
            }
        }

        if (ch + 1 < NCH) {
            storeA(cur ^ 1);                      // post-mma; stage retired by prev barrier
            asm volatile("cp.async.wait_group 0;");
            __syncthreads();                       // publish stage cur^1 to all warps
        }
    }

    // ---- epilogue: bias add, store, optional per-column stats ----
    const int erow = lane >> 2;
    const int ecol = (lane & 3) * 2;
    float cs[8], cq[8];
    #pragma unroll
    for (int i = 0; i < 8; ++i) { cs[i] = 0.f; cq[i] = 0.f; }

    #pragma unroll
    for (int mt = 0; mt < 2; ++mt) {
        #pragma unroll
        for (int nt = 0; nt < 4; ++nt) {
            const int col = noff + nt*8 + ecol;
            const float b0 = s_bias[col], b1 = s_bias[col + 1];
            const int row = n0 + moff + mt*16 + erow;
            float* base = C + (size_t)row * DD + c0 + col;
            const float v00 = d[mt][nt][0] + b0, v01 = d[mt][nt][1] + b1;
            const float v10 = d[mt][nt][2] + b0, v11 = d[mt][nt][3] + b1;
            *(float2*)base          = make_float2(v00, v01);
            *(float2*)(base + 8*DD) = make_float2(v10, v11);
            if (STATS) {
                float w00 = v00, w01 = v01, w10 = v10, w11 = v11;
                if (STATS == 2) {
                    const float* qb = D2 + (size_t)row * DD + c0 + col;
                    float2 qa = *(const float2*)qb;
                    float2 qc = *(const float2*)(qb + 8*DD);
                    w00 -= qa.x; w01 -= qa.y; w10 -= qc.x; w11 -= qc.y;
                }
                cs[nt*2+0] += w00 + w10;  cq[nt*2+0] += w00*w00 + w10*w10;
                cs[nt*2+1] += w01 + w11;  cq[nt*2+1] += w01*w01 + w11*w11;
            }
        }
    }

    if (STATS) {
        #pragma unroll
        for (int o = 4; o <= 16; o <<= 1) {
            #pragma unroll
            for (int i = 0; i < 8; ++i) {
                cs[i] += __shfl_xor_sync(0xffffffffu, cs[i], o);
                cq[i] += __shfl_xor_sync(0xffffffffu, cq[i], o);
            }
        }
        __syncthreads();     // all mma-phase smem reads done before s_sum reuse
        if (lane < 4) {
            #pragma unroll
            for (int nt = 0; nt < 4; ++nt) {
                #pragma unroll
                for (int q = 0; q < 2; ++q) {
                    const int c = noff + nt*8 + lane*2 + q;
                    s_sum[mw*64 + c] = cs[nt*2+q];
                    s_sq [mw*64 + c] = cq[nt*2+q];
                }
            }
        }
        __syncthreads();
        if (tid < 64) {
            float s = s_sum[tid] + s_sum[64+tid] + s_sum[128+tid] + s_sum[192+tid];
            float q = s_sq [tid] + s_sq [64+tid] + s_sq [128+tid] + s_sq [192+tid];
            g_psum[blockIdx.x][0][c0 + tid] = s;
            g_psum[blockIdx.x][1][c0 + tid] = q;
        }
    }
}

// ===========================================================================
// stats reduce: 512 CTA partials -> 32 -> scale/shift
// ===========================================================================
__global__ void stats_mid_k()
{
    const int r = blockIdx.x;
    const int t = threadIdx.x;
    float s = 0.f, q = 0.f;
    #pragma unroll
    for (int i = 0; i < 16; ++i) {
        s += g_psum[r*16 + i][0][t];
        q += g_psum[r*16 + i][1][t];
    }
    g_pmid[r][0][t] = s;
    g_pmid[r][1][t] = q;
}

__global__ void stats_final_k(const float* __restrict__ gamma, const float* __restrict__ beta)
{
    const int t = threadIdx.x;
    float s = 0.f, q = 0.f;
    #pragma unroll
    for (int c = 0; c < 32; ++c) { s += g_pmid[c][0][t]; q += g_pmid[c][1][t]; }
    const float inv = 1.f / (float)NROWS;
    const float mean = s * inv;
    const float var  = q * inv - mean * mean;
    const float sc   = rsqrtf(var + EPS) * gamma[t];
    g_scale[t] = sc;
    g_shift[t] = beta[t] - mean * sc;
}

// ===========================================================================
// Online softmax over S fused with V-weighted sum
// ===========================================================================
__global__ void softmax_part_k(const float* __restrict__ W2, const float* __restrict__ V)
{
    const int b  = blockIdx.x;
    const int ch = blockIdx.y;
    const int d  = threadIdx.x;
    const size_t stride = (size_t)BB * DD;
    size_t off = (size_t)(ch * 32) * stride + (size_t)b * DD + d;
    float m = -INFINITY, l = 0.f, a = 0.f;
    for (int s = 0; s < 32; ++s) {
        const float w  = W2[off];
        const float vv = V[off];
        const float nm = fmaxf(m, w);
        const float e1 = expf(m - nm);
        const float e2 = expf(w - nm);
        l = l * e1 + e2;
        a = a * e1 + e2 * vv;
        m = nm;
        off += stride;
    }
    g_sm_m[ch][b][d] = m;
    g_sm_l[ch][b][d] = l;
    g_sm_a[ch][b][d] = a;
}

__global__ void softmax_final_k(int head)
{
    const int b = blockIdx.x;
    const int d = threadIdx.x;
    float M = -INFINITY;
    #pragma unroll
    for (int c = 0; c < 64; ++c) M = fmaxf(M, g_sm_m[c][b][d]);
    float L = 0.f, A = 0.f;
    #pragma unroll
    for (int c = 0; c < 64; ++c) {
        const float e = expf(g_sm_m[c][b][d] - M);
        L += g_sm_l[c][b][d] * e;
        A += g_sm_a[c][b][d] * e;
    }
    g_headout[b][head * DD + d] = A / L;
}

// ===========================================================================
// Final tiny MLP
// ===========================================================================
template<bool RELU, int E>
__global__ void mlp_k(const float* __restrict__ X, const float* __restrict__ W,
                      const float* __restrict__ bias, float* __restrict__ out)
{
    __shared__ float sw[E];
    __shared__ float red[4];
    const int j = blockIdx.x;
    const int t = threadIdx.x;
    for (int e = t; e < E; e += 128) sw[e] = W[(size_t)j * E + e];
    __syncthreads();
    for (int b = 0; b < BB; ++b) {
        float p = 0.f;
        for (int e = t; e < E; e += 128) p += X[(size_t)b * E + e] * sw[e];
        #pragma unroll
        for (int o = 16; o; o >>= 1) p += __shfl_xor_sync(0xffffffffu, p, o);
        if ((t & 31) == 0) red[t >> 5] = p;
        __syncthreads();
        if (t == 0) {
            float r = red[0] + red[1] + red[2] + red[3] + bias[j];
            if (RELU) r = fmaxf(r, 0.f);
            out[(size_t)b * DD + j] = r;
        }
        __syncthreads();
    }
}

// ===========================================================================
extern "C" void kernel_launch(void* const* d_in, const int* in_sizes, int n_in,
                              void* d_out, int out_size)
{
    (void)in_sizes; (void)n_in; (void)out_size;
    const float* q   = (const float*)d_in[0];
    const float* k   = (const float*)d_in[1];
    const float* v   = (const float*)d_in[2];
    const float* wq  = (const float*)d_in[3];
    const float* bq  = (const float*)d_in[4];
    const float* wk  = (const float*)d_in[5];
    const float* bk  = (const float*)d_in[6];
    const float* wv  = (const float*)d_in[7];
    const float* bv  = (const float*)d_in[8];
    const float* g1  = (const float*)d_in[9];
    const float* be1 = (const float*)d_in[10];
    const float* wl1 = (const float*)d_in[11];
    const float* bl1 = (const float*)d_in[12];
    const float* g2  = (const float*)d_in[13];
    const float* be2 = (const float*)d_in[14];
    const float* wl2 = (const float*)d_in[15];
    const float* bl2 = (const float*)d_in[16];
    const float* mw0 = (const float*)d_in[17];
    const float* mb0 = (const float*)d_in[18];
    const float* mw1 = (const float*)d_in[19];
    const float* mb1 = (const float*)d_in[20];
    const float* mw2 = (const float*)d_in[21];
    const float* mb2 = (const float*)d_in[22];
    float* out = (float*)d_out;

    float *buf = nullptr, *headout = nullptr, *m0 = nullptr, *m1 = nullptr;
    __nv_bfloat16 *whi = nullptr, *wlo = nullptr;
    cudaGetSymbolAddress((void**)&buf,     g_buf);
    cudaGetSymbolAddress((void**)&headout, g_headout);
    cudaGetSymbolAddress((void**)&m0,      g_mlp0);
    cudaGetSymbolAddress((void**)&m1,      g_mlp1);
    cudaGetSymbolAddress((void**)&whi,     g_whi);
    cudaGetSymbolAddress((void**)&wlo,     g_wlo);

    static bool attr_done = false;
    if (!attr_done) {
        cudaFuncSetAttribute(gemm_mma<0,0>, cudaFuncAttributeMaxDynamicSharedMemorySize, GSMEM);
        cudaFuncSetAttribute(gemm_mma<0,2>, cudaFuncAttributeMaxDynamicSharedMemorySize, GSMEM);
        cudaFuncSetAttribute(gemm_mma<1,1>, cudaFuncAttributeMaxDynamicSharedMemorySize, GSMEM);
        cudaFuncSetAttribute(gemm_mma<2,0>, cudaFuncAttributeMaxDynamicSharedMemorySize, GSMEM);
        attr_done = true;
    }

    const size_t SZ = (size_t)NROWS * DD;
    dim3 ggrid(NROWS / BM, DD / BNT);     // (512, 4)

    wconv_k<<<(5 * HH * DD * DD) / 256, 256>>>(wq, wk, wv, wl1, wl2);

    const float* Qc = q; const float* Kc = k; const float* Vc = v;
    for (int h = 0; h < HH; ++h) {
        float* Qn = buf + (size_t)(0 + (h & 1)) * SZ;
        float* Kn = buf + (size_t)(2 + (h & 1)) * SZ;
        float* Vn = buf + (size_t)(4 + (h & 1)) * SZ;
        float* T1 = buf + 6 * SZ;
        float* T2 = buf + 7 * SZ;
        const size_t wsz = (size_t)DD * DD;
        const __nv_bfloat16* Wq_h = whi + (h*5 + 0) * wsz; const __nv_bfloat16* Wq_l = wlo + (h*5 + 0) * wsz;
        const __nv_bfloat16* Wk_h = whi + (h*5 + 1) * wsz; const __nv_bfloat16* Wk_l = wlo + (h*5 + 1) * wsz;
        const __nv_bfloat16* Wv_h = whi + (h*5 + 2) * wsz; const __nv_bfloat16* Wv_l = wlo + (h*5 + 2) * wsz;
        const __nv_bfloat16* W1_h = whi + (h*5 + 3) * wsz; const __nv_bfloat16* W1_l = wlo + (h*5 + 3) * wsz;
        const __nv_bfloat16* W2_h = whi + (h*5 + 4) * wsz; const __nv_bfloat16* W2_l = wlo + (h*5 + 4) * wsz;

        // projections; K-GEMM fuses BN1 diff-stats vs Qn
        gemm_mma<0,0><<<ggrid, 256, GSMEM>>>(Qc, nullptr, nullptr, Wq_h, Wq_l, bq + h*DD, Qn);
        gemm_mma<0,2><<<ggrid, 256, GSMEM>>>(Kc, nullptr, Qn,      Wk_h, Wk_l, bk + h*DD, Kn);
        gemm_mma<0,0><<<ggrid, 256, GSMEM>>>(Vc, nullptr, nullptr, Wv_h, Wv_l, bv + h*DD, Vn);
        stats_mid_k<<<32, 256>>>();
        stats_final_k<<<1, 256>>>(g1 + h*DD, be1 + h*DD);

        // relu(bn1(K-Q)) @ wl1^T + bl1, fused self-stats for BN2
        gemm_mma<1,1><<<ggrid, 256, GSMEM>>>(Kn, Qn, nullptr, W1_h, W1_l, bl1 + h*DD, T1);
        stats_mid_k<<<32, 256>>>();
        stats_final_k<<<1, 256>>>(g2 + h*DD, be2 + h*DD);

        // relu(bn2(T1)) @ wl2^T + bl2
        gemm_mma<2,0><<<ggrid, 256, GSMEM>>>(T1, nullptr, nullptr, W2_h, W2_l, bl2 + h*DD, T2);

        softmax_part_k<<<dim3(BB, 64), DD>>>(T2, Vn);
        softmax_final_k<<<BB, DD>>>(h);

        Qc = Qn; Kc = Kn; Vc = Vn;
    }

    mlp_k<true,  HH*DD><<<DD, 128>>>(headout, mw0, mb0, m0);
    mlp_k<true,  DD   ><<<DD, 128>>>(m0,      mw1, mb1, m1);
    mlp_k<false, DD   ><<<DD, 128>>>(m1,      mw2, mb2, out);
}